// round 13
// baseline (speedup 1.0000x reference)
#include <cuda_runtime.h>

// Problem constants (fixed shapes)
#define BB   2
#define HD   4
#define HH   128
#define WW   128
#define KS   7
#define KK   49
#define NSP  9
#define SS   64
#define PLANE (HH * WW)

// Four pixels per warp: group g = lane>>3 handles pixel (h, w0+g).
// COLUMN ownership: lane t (t<7) owns window column t (k = 7r + t).
// Lane 7 carries the eps seed only.
// sp processed in 3 chunks of 3 (per-sp normalization is independent;
// outputs just sum) -> live gather state 24 regs instead of 72 ->
// fits 5 CTAs/SM (launch_bounds 128,5) for +25% occupancy.
// attn (raw) hoisted for all heads; exp recomputed per chunk (MUFU is cheap).
__global__ __launch_bounds__(128, 5)
void attn_reweight_kernel(const float* __restrict__ attn,
                          const float* __restrict__ sims,
                          const int*   __restrict__ sinds,
                          float*       __restrict__ out)
{
    const int warpid = blockIdx.x * (blockDim.x >> 5) + (threadIdx.x >> 5);
    const int lane   = threadIdx.x & 31;
    const int g      = lane >> 3;
    const int t      = lane & 7;
    const bool act   = (t < 7);

    const int pix0 = warpid << 2;
    const int b    = pix0 >> 14;
    const int idx  = pix0 & 16383;
    const int h    = idx >> 7;
    const int w    = (idx & 127) + g;        // idx&127 multiple of 4

    const int hs = min(max(h - KS / 2, 0), HH - KS);
    const int ws = min(max(w - KS / 2, 0), WW - KS);

    const int   wbase = hs * WW + ws + (act ? t : 6);   // lane 7: safe addr
    const float eps0  = act ? 0.0f : 1e-10f;            // eps seed on lane 7

    const float* sb   = sims + b * (SS * PLANE);
    const int    offc = h * WW + w;                     // center (pi)

    // sinds: coalesced per-group loads, distribute via shfl
    const int sbase = (pix0 + g) * NSP;
    const int ind_a = __ldg(&sinds[sbase + t]);
    const int ind_b = (t == 0) ? __ldg(&sinds[sbase + 8]) : 0;

    // ---- hoisted raw attn for all heads (overlaps gather latency) ----
    const int base0      = (((b * HD) * HH + h) * WW + w) * KK;
    const int headStride = HH * WW * KK;
    float va[HD][7];
#pragma unroll
    for (int hd = 0; hd < HD; ++hd) {
        const float* ab = attn + base0 + hd * headStride + t;   // k = 7r + t
#pragma unroll
        for (int r = 0; r < 7; ++r)
            va[hd][r] = act ? __ldg(ab + 7 * r) : -1e30f;
    }

    // cross-chunk output accumulators
    float o_[HD][7];
#pragma unroll
    for (int hd = 0; hd < HD; ++hd)
#pragma unroll
        for (int r = 0; r < 7; ++r)
            o_[hd][r] = 0.0f;

    // ---- 3 chunks of 3 superpixels ----
#pragma unroll
    for (int c = 0; c < 3; ++c) {
        // gather 3 planes (+ centers)
        float p[7][3], pic[3];
#pragma unroll
        for (int j = 0; j < 3; ++j) {
            const int sp  = 3 * c + j;
            const int gid = (sp < 8)
                ? __shfl_sync(0xffffffffu, ind_a, (g << 3) + sp)
                : __shfl_sync(0xffffffffu, ind_b, (g << 3));
            const float* pl = sb + gid * PLANE;
#pragma unroll
            for (int r = 0; r < 7; ++r)
                p[r][j] = act ? __ldg(pl + wbase + r * WW) : 0.0f;
            pic[j] = __ldg(pl + offc);
        }

#pragma unroll
        for (int hd = 0; hd < HD; ++hd) {
            float a[7];
#pragma unroll
            for (int r = 0; r < 7; ++r)
                a[r] = __expf(va[hd][r]);        // 0 on lane 7

            // d[j] = eps + sum_k a_k p_j[k]; dual accumulators + butterfly
            float d[3];
#pragma unroll
            for (int j = 0; j < 3; ++j) {
                float acc0 = fmaf(a[0], p[0][j], eps0);
                float acc1 = a[1] * p[1][j];
                acc0 = fmaf(a[2], p[2][j], acc0);
                acc1 = fmaf(a[3], p[3][j], acc1);
                acc0 = fmaf(a[4], p[4][j], acc0);
                acc1 = fmaf(a[5], p[5][j], acc1);
                acc0 = fmaf(a[6], p[6][j], acc0);
                d[j] = acc0 + acc1;
            }
#pragma unroll
            for (int o = 4; o > 0; o >>= 1) {
#pragma unroll
                for (int j = 0; j < 3; ++j)
                    d[j] += __shfl_xor_sync(0xffffffffu, d[j], o);
            }

            // w_j = pi_j / d_j; paired rcp for d0,d1 + single for d2
            float w0, w1, w2;
            {
                const float prod = d[0] * d[1];
                float rp;
                asm("rcp.approx.f32 %0, %1;" : "=f"(rp) : "f"(prod));
                w0 = pic[0] * (rp * d[1]);
                w1 = pic[1] * (rp * d[0]);
                float r2;
                asm("rcp.approx.f32 %0, %1;" : "=f"(r2) : "f"(d[2]));
                w2 = pic[2] * r2;
            }

            // accumulate output partials
#pragma unroll
            for (int r = 0; r < 7; ++r) {
                float acc = fmaf(w0, p[r][0], o_[hd][r]);
                acc = fmaf(w1, p[r][1], acc);
                o_[hd][r] = fmaf(w2, p[r][2], acc);
            }

            // last chunk: finalize and store
            if (c == 2 && act) {
                float* ob = out + base0 + hd * headStride + t;
#pragma unroll
                for (int r = 0; r < 7; ++r)
                    ob[7 * r] = a[r] * o_[hd][r];
            }
        }
    }
}

extern "C" void kernel_launch(void* const* d_in, const int* in_sizes, int n_in,
                              void* d_out, int out_size)
{
    const float* attn  = (const float*)d_in[0];
    const float* sims  = (const float*)d_in[1];
    const int*   sinds = (const int*)d_in[2];
    float*       out   = (float*)d_out;

    const int warps   = BB * HH * WW / 4;        // 8192 warps (4 pixels each)
    const int threads = 128;                     // 4 warps / CTA
    const int blocks  = warps / (threads / 32);  // 2048
    attn_reweight_kernel<<<blocks, threads>>>(attn, sims, sinds, out);
}

// round 14
// speedup vs baseline: 1.3106x; 1.3106x over previous
#include <cuda_runtime.h>

// Problem constants (fixed shapes)
#define BB   2
#define HD   4
#define HH   128
#define WW   128
#define KS   7
#define KK   49
#define NSP  9
#define SS   64
#define PLANE (HH * WW)

// Four pixels per warp: group g = lane>>3 handles pixel (h, w0+g).
// COLUMN ownership: lane t (t<7) owns window column t (k = 7r + t).
// Lane 7 carries the eps seed.
// Denominators via 8-lane reduce-scatter (lane t ends with D[sp=t]);
// sp=8 via 3-stage butterfly. pi: lane t's own ind_a IS sp-t's plane -> 1 LDG.
// All 63+ gather LDGs stay in one up-front burst (max MLP — do not chunk).
__global__ __launch_bounds__(128, 5)
void attn_reweight_kernel(const float* __restrict__ attn,
                          const float* __restrict__ sims,
                          const int*   __restrict__ sinds,
                          float*       __restrict__ out)
{
    const int warpid = blockIdx.x * (blockDim.x >> 5) + (threadIdx.x >> 5);
    const int lane   = threadIdx.x & 31;
    const int g      = lane >> 3;
    const int t      = lane & 7;
    const bool act   = (t < 7);

    const int pix0 = warpid << 2;
    const int b    = pix0 >> 14;
    const int idx  = pix0 & 16383;
    const int h    = idx >> 7;
    const int w    = (idx & 127) + g;        // idx&127 multiple of 4

    const int hs = min(max(h - KS / 2, 0), HH - KS);
    const int ws = min(max(w - KS / 2, 0), WW - KS);

    const int   wbase = hs * WW + ws + (act ? t : 6);   // lane 7: safe addr
    const float eps0  = act ? 0.0f : 1e-10f;            // eps seed on lane 7

    const float* sb   = sims + b * (SS * PLANE);
    const int    offc = h * WW + w;                     // center (pi)

    // sinds: lane t loads gid of sp=t; lane 7 additionally sp=8
    const int sbase = (pix0 + g) * NSP;
    const int ind_a = __ldg(&sinds[sbase + t]);
    const int ind_b = (t == 7) ? __ldg(&sinds[sbase + 8]) : 0;

    // ---- gather 9 planes in one burst (keep MLP!) ----
    float p[7][NSP];
#pragma unroll
    for (int sp = 0; sp < NSP; ++sp) {
        const int src = (g << 3) + ((sp < 8) ? sp : 7);
        const int gid = __shfl_sync(0xffffffffu, (sp < 8) ? ind_a : ind_b, src);
        const float* pl = sb + gid * PLANE;
#pragma unroll
        for (int r = 0; r < 7; ++r)
            p[r][sp] = act ? __ldg(pl + wbase + r * WW) : 0.0f;
    }
    // centers: lane t owns pi[sp=t]; pi[8] broadcast once (head-invariant)
    const float pi_own = __ldg(sb + ind_a * PLANE + offc);
    const float pi8l   = (t == 7) ? __ldg(sb + ind_b * PLANE + offc) : 0.0f;
    const float pib8   = __shfl_sync(0xffffffffu, pi8l, (g << 3) + 7);

    // ---- per-head compute ----
#pragma unroll
    for (int hd = 0; hd < HD; ++hd) {
        const int base = (((b * HD + hd) * HH + h) * WW + w) * KK;
        const float* ab = attn + base + t;              // k = 7r + t

        float a[7];
#pragma unroll
        for (int r = 0; r < 7; ++r)
            a[r] = __expf(act ? __ldg(ab + 7 * r) : -1e30f);   // 0 on lane 7

        // per-lane partials: d[sp] = (lane==7 ? eps : 0) + sum_r a_r p[r][sp]
        float d[NSP];
#pragma unroll
        for (int sp = 0; sp < NSP; ++sp) {
            float acc0 = fmaf(a[0], p[0][sp], eps0);
            float acc1 = a[1] * p[1][sp];
            acc0 = fmaf(a[2], p[2][sp], acc0);
            acc1 = fmaf(a[3], p[3][sp], acc1);
            acc0 = fmaf(a[4], p[4][sp], acc0);
            acc1 = fmaf(a[5], p[5][sp], acc1);
            acc0 = fmaf(a[6], p[6][sp], acc0);
            d[sp] = acc0 + acc1;
        }

        // reduce-scatter sp 0..7 within each 8-lane group: lane t ends with D[t]
        float v4[4];
#pragma unroll
        for (int j = 0; j < 4; ++j) {
            const float send = (t & 4) ? d[j] : d[j + 4];
            const float keep = (t & 4) ? d[j + 4] : d[j];
            v4[j] = keep + __shfl_xor_sync(0xffffffffu, send, 4);
        }
        float v2[2];
#pragma unroll
        for (int j = 0; j < 2; ++j) {
            const float send = (t & 2) ? v4[j] : v4[j + 2];
            const float keep = (t & 2) ? v4[j + 2] : v4[j];
            v2[j] = keep + __shfl_xor_sync(0xffffffffu, send, 2);
        }
        float D;
        {
            const float send = (t & 1) ? v2[0] : v2[1];
            const float keep = (t & 1) ? v2[1] : v2[0];
            D = keep + __shfl_xor_sync(0xffffffffu, send, 1);
        }
        // sp=8: full butterfly (all lanes)
        float d8 = d[8];
#pragma unroll
        for (int o = 4; o > 0; o >>= 1)
            d8 += __shfl_xor_sync(0xffffffffu, d8, o);

        // per-lane weight, then broadcast
        float rD, r8;
        asm("rcp.approx.f32 %0, %1;" : "=f"(rD) : "f"(D));
        asm("rcp.approx.f32 %0, %1;" : "=f"(r8) : "f"(d8));
        const float w_own = pi_own * rD;
        const float w8    = pib8 * r8;

        float wb[8];
#pragma unroll
        for (int sp = 0; sp < 8; ++sp)
            wb[sp] = __shfl_sync(0xffffffffu, w_own, (g << 3) + sp);

        // out_k = a_k * sum_sp w_sp p_sp[k]
        float o_[7];
#pragma unroll
        for (int r = 0; r < 7; ++r)
            o_[r] = w8 * p[r][8];
#pragma unroll
        for (int sp = 0; sp < 8; ++sp) {
#pragma unroll
            for (int r = 0; r < 7; ++r)
                o_[r] = fmaf(wb[sp], p[r][sp], o_[r]);
        }

        float* ob = out + base + t;
        if (act) {
#pragma unroll
            for (int r = 0; r < 7; ++r)
                ob[7 * r] = a[r] * o_[r];
        }
    }
}

extern "C" void kernel_launch(void* const* d_in, const int* in_sizes, int n_in,
                              void* d_out, int out_size)
{
    const float* attn  = (const float*)d_in[0];
    const float* sims  = (const float*)d_in[1];
    const int*   sinds = (const int*)d_in[2];
    float*       out   = (float*)d_out;

    const int warps   = BB * HH * WW / 4;        // 8192 warps (4 pixels each)
    const int threads = 128;                     // 4 warps / CTA
    const int blocks  = warps / (threads / 32);  // 2048
    attn_reweight_kernel<<<blocks, threads>>>(attn, sims, sinds, out);
}